// round 4
// baseline (speedup 1.0000x reference)
#include <cuda_runtime.h>
#include <math.h>

// Normalized W lives here: 2 rows x 512 cols
__device__ float g_Wn[2 * 512];

static constexpr float EPS_CLIP = 1e-7f;
static constexpr float SCALE    = 64.0f;
// cos(0.5), sin(0.5)
static constexpr float COS_M = 0.8775825618903728f;
static constexpr float SIN_M = 0.479425538604203f;

// ---------------------------------------------------------------------------
// Prologue: L2-normalize W rows (C=2, D=512) into g_Wn.
// ---------------------------------------------------------------------------
__global__ void normalize_w_kernel(const float* __restrict__ W) {
    const int row = blockIdx.x;            // 0 or 1
    const int tid = threadIdx.x;           // 0..127
    const float* wrow = W + row * 512;

    float ss = 0.0f;
    #pragma unroll
    for (int i = tid; i < 512; i += 128) {
        float v = wrow[i];
        ss += v * v;
    }
    #pragma unroll
    for (int o = 16; o > 0; o >>= 1) ss += __shfl_xor_sync(0xffffffff, ss, o);

    __shared__ float warp_ss[4];
    __shared__ float s_inv;
    const int lane = tid & 31;
    const int wid  = tid >> 5;
    if (lane == 0) warp_ss[wid] = ss;
    __syncthreads();
    if (tid == 0) {
        float tot = warp_ss[0] + warp_ss[1] + warp_ss[2] + warp_ss[3];
        s_inv = 1.0f / fmaxf(sqrtf(tot), 1e-12f);
    }
    __syncthreads();

    const float inv = s_inv;
    #pragma unroll
    for (int i = tid; i < 512; i += 128) {
        g_Wn[row * 512 + i] = wrow[i] * inv;
    }
}

// ---------------------------------------------------------------------------
// Main: one warp per feature row. Each lane loads 4 float4 (16 floats) of
// the 512-float row — fully coalesced 128B transactions. Accumulate ||f||^2
// and two dots against normalized class vectors, warp-reduce, apply margin.
// ---------------------------------------------------------------------------
__global__ void __launch_bounds__(256, 8)
arcface_kernel(const float* __restrict__ feat,
               const int* __restrict__ label,     // int32 labels
               float* __restrict__ out)
{
    const int gwarp = (blockIdx.x * blockDim.x + threadIdx.x) >> 5;  // row id
    const int lane  = threadIdx.x & 31;

    const float4* __restrict__ f  = reinterpret_cast<const float4*>(
        feat + (size_t)gwarp * 512);
    const float4* __restrict__ w0 = reinterpret_cast<const float4*>(g_Wn);
    const float4* __restrict__ w1 = reinterpret_cast<const float4*>(g_Wn + 512);

    float ss = 0.0f, d0 = 0.0f, d1 = 0.0f;

    #pragma unroll
    for (int k = 0; k < 4; k++) {
        const int idx = lane + 32 * k;       // 128 float4 per row
        float4 a = f[idx];
        float4 b = w0[idx];
        float4 c = w1[idx];
        ss = fmaf(a.x, a.x, ss); ss = fmaf(a.y, a.y, ss);
        ss = fmaf(a.z, a.z, ss); ss = fmaf(a.w, a.w, ss);
        d0 = fmaf(a.x, b.x, d0); d0 = fmaf(a.y, b.y, d0);
        d0 = fmaf(a.z, b.z, d0); d0 = fmaf(a.w, b.w, d0);
        d1 = fmaf(a.x, c.x, d1); d1 = fmaf(a.y, c.y, d1);
        d1 = fmaf(a.z, c.z, d1); d1 = fmaf(a.w, c.w, d1);
    }

    #pragma unroll
    for (int o = 16; o > 0; o >>= 1) {
        ss += __shfl_xor_sync(0xffffffff, ss, o);
        d0 += __shfl_xor_sync(0xffffffff, d0, o);
        d1 += __shfl_xor_sync(0xffffffff, d1, o);
    }

    if (lane == 0) {
        const float inv = 1.0f / fmaxf(sqrtf(ss), 1e-12f);

        float c0 = fminf(fmaxf(d0 * inv, -1.0f + EPS_CLIP), 1.0f - EPS_CLIP);
        float c1 = fminf(fmaxf(d1 * inv, -1.0f + EPS_CLIP), 1.0f - EPS_CLIP);

        // cos(theta + m) = cos*cos_m - sin*sin_m, sin = sqrt(1-cos^2) >= 0
        float s0 = sqrtf(fmaxf(1.0f - c0 * c0, 0.0f));
        float s1 = sqrtf(fmaxf(1.0f - c1 * c1, 0.0f));
        float m0 = c0 * COS_M - s0 * SIN_M;
        float m1 = c1 * COS_M - s1 * SIN_M;

        const int lab = label[gwarp];
        float o0 = (lab == 0) ? m0 : c0;
        float o1 = (lab == 1) ? m1 : c1;

        float2 ov = make_float2(o0 * SCALE, o1 * SCALE);
        reinterpret_cast<float2*>(out)[gwarp] = ov;
    }
}

// ---------------------------------------------------------------------------
// kernel_launch: identify inputs by element count (robust to ordering):
//   feat  : B*D = 67,108,864 f32
//   W     : C*D = 1,024      f32
//   label : B   = 131,072    int32
// out: [B*C] f32.
// ---------------------------------------------------------------------------
extern "C" void kernel_launch(void* const* d_in, const int* in_sizes, int n_in,
                              void* d_out, int out_size)
{
    const float* feat  = nullptr;
    const float* W     = nullptr;
    const int*   label = nullptr;
    int B = 0;

    // Pick largest = feat, smallest = W, remaining = label.
    int i_feat = 0, i_w = 0, i_lab = 0;
    for (int i = 1; i < n_in; i++) {
        if (in_sizes[i] > in_sizes[i_feat]) i_feat = i;
        if (in_sizes[i] < in_sizes[i_w])    i_w    = i;
    }
    for (int i = 0; i < n_in; i++)
        if (i != i_feat && i != i_w) i_lab = i;

    feat  = (const float*)d_in[i_feat];
    W     = (const float*)d_in[i_w];
    label = (const int*)d_in[i_lab];
    B     = in_sizes[i_lab];

    normalize_w_kernel<<<2, 128>>>(W);

    const int rows_per_block = 256 / 32;   // 8 warps (rows) per block
    const int blocks = (B + rows_per_block - 1) / rows_per_block;
    arcface_kernel<<<blocks, 256>>>(feat, label, out_size ? (float*)d_out : (float*)d_out);
}